// round 12
// baseline (speedup 1.0000x reference)
#include <cuda_runtime.h>
#include <cstdint>

#define N_NODES 100000
#define N_EDGES 1000000
#define IN_CH   32
#define EDGE_CH 16
#define OUT_CH  32
#define D_MID   56

typedef unsigned long long u64;

static __device__ int g_is64;
static __device__ __align__(16) float g_XR[N_NODES * D_MID];  // x@W1[0:32]+b1
static __device__ __align__(16) float g_XC[N_NODES * D_MID];  // x@W1[32:64]
static __device__ __align__(16) float4 g_H[14 * N_EDGES];     // H[q][e], k = 4q+u

// ---- packed f32x2 helpers ---------------------------------------------------
__device__ __forceinline__ u64 pk2(float a, float b) {
    u64 r; asm("mov.b64 %0, {%1,%2};" : "=l"(r) : "f"(a), "f"(b)); return r;
}
__device__ __forceinline__ void upk2(float& a, float& b, u64 v) {
    asm("mov.b64 {%0,%1}, %2;" : "=f"(a), "=f"(b) : "l"(v));
}
#define FMA2(d, a, b, c) asm("fma.rn.f32x2 %0, %1, %2, %3;" : "=l"(d) : "l"(a), "l"(b), "l"(c))
#define MUL2(d, a, b)    asm("mul.rn.f32x2 %0, %1, %2;"     : "=l"(d) : "l"(a), "l"(b))
#define ADD2(d, a, b)    asm("add.rn.f32x2 %0, %1, %2;"     : "=l"(d) : "l"(a), "l"(b))

__device__ __forceinline__ void atomicMaxF(float* addr, float val) {
    if (val >= 0.0f) atomicMax(reinterpret_cast<int*>(addr), __float_as_int(val));
    else             atomicMin(reinterpret_cast<unsigned int*>(addr), __float_as_uint(val));
}

// ---------------------------------------------------------------------------
// K0: init output to -inf + (block 0) detect int64 vs int32 edge_index
// ---------------------------------------------------------------------------
__global__ void k_pre(const unsigned int* __restrict__ w, unsigned int* __restrict__ out) {
    if (blockIdx.x == 0) {
        __shared__ int bad;
        if (threadIdx.x == 0) bad = 0;
        __syncthreads();
        for (int i = threadIdx.x; i < 4096; i += blockDim.x)
            if (w[2 * i + 1] != 0u) bad = 1;   // benign race
        __syncthreads();
        if (threadIdx.x == 0) g_is64 = !bad;
    }
    int stride = gridDim.x * blockDim.x;
    for (int i = blockIdx.x * blockDim.x + threadIdx.x; i < N_NODES * OUT_CH; i += stride)
        out[i] = 0xFF800000u;  // -inf
}

// ---------------------------------------------------------------------------
// K1: per-node precompute (scalar fp32, j-blocked — proven round 6)
// ---------------------------------------------------------------------------
__global__ void __launch_bounds__(128, 8) k_node(const float* __restrict__ x,
                                                 const float* __restrict__ W1,
                                                 const float* __restrict__ b1) {
    __shared__ __align__(16) float sW[2 * IN_CH * D_MID];
    __shared__ __align__(16) float sb[D_MID];
    for (int i = threadIdx.x; i < 2 * IN_CH * D_MID; i += blockDim.x) sW[i] = W1[i];
    for (int i = threadIdx.x; i < D_MID; i += blockDim.x) sb[i] = b1[i];
    __syncthreads();

    int n = blockIdx.x * blockDim.x + threadIdx.x;
    if (n >= N_NODES) return;

    float xr[IN_CH];
    const float4* xp = reinterpret_cast<const float4*>(x + n * IN_CH);
#pragma unroll
    for (int c = 0; c < 8; c++) {
        float4 v = xp[c];
        xr[4 * c + 0] = v.x; xr[4 * c + 1] = v.y; xr[4 * c + 2] = v.z; xr[4 * c + 3] = v.w;
    }

#pragma unroll
    for (int which = 0; which < 2; which++) {
        float* dstbase = (which == 0 ? g_XR : g_XC) + (size_t)n * D_MID;
        const float* Wbase = sW + which * IN_CH * D_MID;
#pragma unroll
        for (int jb = 0; jb < D_MID / 8; jb++) {
            u64 hb0, hb1, hb2, hb3;
            if (which == 0) {
                const ulonglong2* bp = reinterpret_cast<const ulonglong2*>(&sb[8 * jb]);
                ulonglong2 b01 = bp[0], b23 = bp[1];
                hb0 = b01.x; hb1 = b01.y; hb2 = b23.x; hb3 = b23.y;
            } else {
                hb0 = hb1 = hb2 = hb3 = 0ull;
            }
#pragma unroll
            for (int k = 0; k < IN_CH; k++) {
                u64 aa = pk2(xr[k], xr[k]);
                const ulonglong2* w = reinterpret_cast<const ulonglong2*>(Wbase + k * D_MID + 8 * jb);
                ulonglong2 w0 = w[0], w1 = w[1];
                FMA2(hb0, aa, w0.x, hb0);
                FMA2(hb1, aa, w0.y, hb1);
                FMA2(hb2, aa, w1.x, hb2);
                FMA2(hb3, aa, w1.y, hb3);
            }
            ulonglong2* dst = reinterpret_cast<ulonglong2*>(dstbase + 8 * jb);
            ulonglong2 s0; s0.x = hb0; s0.y = hb1;
            ulonglong2 s1; s1.x = hb2; s1.y = hb3;
            dst[0] = s0; dst[1] = s1;
        }
    }
}

// ---------------------------------------------------------------------------
// K2a: layer 1 -> H.  2 edges/thread, j-blocked chunks, weight LDS shared.
// ---------------------------------------------------------------------------
__global__ void __launch_bounds__(128) k_e1(const int* __restrict__ idx32,
                                            const float* __restrict__ ea,
                                            const float* __restrict__ W1) {
    __shared__ __align__(16) float sWe[EDGE_CH * D_MID];   // 3584 B
    const float* We = W1 + 2 * IN_CH * D_MID;
    for (int i = threadIdx.x; i < EDGE_CH * D_MID; i += blockDim.x) sWe[i] = We[i];
    __syncthreads();

    const int tid = threadIdx.x;
    int e0 = blockIdx.x * 256 + tid;
    int e1 = e0 + 128;
    bool v0 = e0 < N_EDGES, v1 = e1 < N_EDGES;
    int ec0 = v0 ? e0 : N_EDGES - 1;
    int ec1 = v1 ? e1 : N_EDGES - 1;

    int rol0, col0, rol1, col1;
    if (g_is64) {
        rol0 = idx32[2 * ec0]; col0 = idx32[2 * (N_EDGES + ec0)];
        rol1 = idx32[2 * ec1]; col1 = idx32[2 * (N_EDGES + ec1)];
    } else {
        rol0 = idx32[ec0]; col0 = idx32[N_EDGES + ec0];
        rol1 = idx32[ec1]; col1 = idx32[N_EDGES + ec1];
    }
    const ulonglong2* pr0 = reinterpret_cast<const ulonglong2*>(g_XR + (size_t)rol0 * D_MID);
    const ulonglong2* pc0 = reinterpret_cast<const ulonglong2*>(g_XC + (size_t)col0 * D_MID);
    const ulonglong2* pr1 = reinterpret_cast<const ulonglong2*>(g_XR + (size_t)rol1 * D_MID);
    const ulonglong2* pc1 = reinterpret_cast<const ulonglong2*>(g_XC + (size_t)col1 * D_MID);

    // edge_attr held in registers for the whole kernel
    float av[2][EDGE_CH];
    {
        const float4* p0 = reinterpret_cast<const float4*>(ea + (size_t)ec0 * EDGE_CH);
        const float4* p1 = reinterpret_cast<const float4*>(ea + (size_t)ec1 * EDGE_CH);
#pragma unroll
        for (int c = 0; c < 4; c++) {
            float4 a = p0[c], b = p1[c];
            av[0][4 * c + 0] = a.x; av[0][4 * c + 1] = a.y;
            av[0][4 * c + 2] = a.z; av[0][4 * c + 3] = a.w;
            av[1][4 * c + 0] = b.x; av[1][4 * c + 1] = b.y;
            av[1][4 * c + 2] = b.z; av[1][4 * c + 3] = b.w;
        }
    }

#pragma unroll
    for (int jb = 0; jb < D_MID / 8; jb++) {
        // gathers for this chunk (issued early, consumed after the FMA block)
        ulonglong2 r0a = pr0[2 * jb], r0b = pr0[2 * jb + 1];
        ulonglong2 c0a = pc0[2 * jb], c0b = pc0[2 * jb + 1];
        ulonglong2 r1a = pr1[2 * jb], r1b = pr1[2 * jb + 1];
        ulonglong2 c1a = pc1[2 * jb], c1b = pc1[2 * jb + 1];

        u64 hb[2][4];
#pragma unroll
        for (int k = 0; k < EDGE_CH; k++) {
            u64 aa0 = pk2(av[0][k], av[0][k]);
            u64 aa1 = pk2(av[1][k], av[1][k]);
            const ulonglong2* w = reinterpret_cast<const ulonglong2*>(&sWe[k * D_MID + 8 * jb]);
            ulonglong2 w0 = w[0], w1 = w[1];     // shared across both edges
            if (k == 0) {
                MUL2(hb[0][0], aa0, w0.x); MUL2(hb[0][1], aa0, w0.y);
                MUL2(hb[0][2], aa0, w1.x); MUL2(hb[0][3], aa0, w1.y);
                MUL2(hb[1][0], aa1, w0.x); MUL2(hb[1][1], aa1, w0.y);
                MUL2(hb[1][2], aa1, w1.x); MUL2(hb[1][3], aa1, w1.y);
            } else {
                FMA2(hb[0][0], aa0, w0.x, hb[0][0]); FMA2(hb[0][1], aa0, w0.y, hb[0][1]);
                FMA2(hb[0][2], aa0, w1.x, hb[0][2]); FMA2(hb[0][3], aa0, w1.y, hb[0][3]);
                FMA2(hb[1][0], aa1, w0.x, hb[1][0]); FMA2(hb[1][1], aa1, w0.y, hb[1][1]);
                FMA2(hb[1][2], aa1, w1.x, hb[1][2]); FMA2(hb[1][3], aa1, w1.y, hb[1][3]);
            }
        }
        // add gathered XR + XC
        ADD2(hb[0][0], hb[0][0], r0a.x); ADD2(hb[0][1], hb[0][1], r0a.y);
        ADD2(hb[0][2], hb[0][2], r0b.x); ADD2(hb[0][3], hb[0][3], r0b.y);
        ADD2(hb[0][0], hb[0][0], c0a.x); ADD2(hb[0][1], hb[0][1], c0a.y);
        ADD2(hb[0][2], hb[0][2], c0b.x); ADD2(hb[0][3], hb[0][3], c0b.y);
        ADD2(hb[1][0], hb[1][0], r1a.x); ADD2(hb[1][1], hb[1][1], r1a.y);
        ADD2(hb[1][2], hb[1][2], r1b.x); ADD2(hb[1][3], hb[1][3], r1b.y);
        ADD2(hb[1][0], hb[1][0], c1a.x); ADD2(hb[1][1], hb[1][1], c1a.y);
        ADD2(hb[1][2], hb[1][2], c1b.x); ADD2(hb[1][3], hb[1][3], c1b.y);

        // LeakyReLU + coalesced store (chunk covers q = 2jb, 2jb+1)
#pragma unroll
        for (int i = 0; i < 2; i++) {
            if (i == 0 ? !v0 : !v1) continue;
            int e = (i == 0) ? e0 : e1;
            float f0, f1, f2, f3, f4, f5, f6, f7;
            upk2(f0, f1, hb[i][0]);
            upk2(f2, f3, hb[i][1]);
            upk2(f4, f5, hb[i][2]);
            upk2(f6, f7, hb[i][3]);
            f0 = fmaxf(f0, 0.01f * f0); f1 = fmaxf(f1, 0.01f * f1);
            f2 = fmaxf(f2, 0.01f * f2); f3 = fmaxf(f3, 0.01f * f3);
            f4 = fmaxf(f4, 0.01f * f4); f5 = fmaxf(f5, 0.01f * f5);
            f6 = fmaxf(f6, 0.01f * f6); f7 = fmaxf(f7, 0.01f * f7);
            g_H[(size_t)(2 * jb) * N_EDGES + e]     = make_float4(f0, f1, f2, f3);
            g_H[(size_t)(2 * jb + 1) * N_EDGES + e] = make_float4(f4, f5, f6, f7);
        }
    }
}

// ---------------------------------------------------------------------------
// K2b: layer 2 + scatter-max.  2 edges/thread, weight LDS shared.
// ---------------------------------------------------------------------------
__global__ void __launch_bounds__(128) k_e2(const int* __restrict__ idx32,
                                            const float* __restrict__ W2,
                                            const float* __restrict__ b2,
                                            float* __restrict__ out) {
    __shared__ __align__(16) float sW2[D_MID * OUT_CH];
    __shared__ __align__(16) float sb2[OUT_CH];
    for (int i = threadIdx.x; i < D_MID * OUT_CH; i += blockDim.x) sW2[i] = W2[i];
    for (int i = threadIdx.x; i < OUT_CH; i += blockDim.x) sb2[i] = b2[i];
    __syncthreads();

    const int tid = threadIdx.x;
    int e0 = blockIdx.x * 256 + tid;
    int e1 = e0 + 128;
    bool v0 = e0 < N_EDGES, v1 = e1 < N_EDGES;
    int ec0 = v0 ? e0 : N_EDGES - 1;
    int ec1 = v1 ? e1 : N_EDGES - 1;

    int col0, col1;
    if (g_is64) {
        col0 = idx32[2 * (N_EDGES + ec0)];
        col1 = idx32[2 * (N_EDGES + ec1)];
    } else {
        col0 = idx32[N_EDGES + ec0];
        col1 = idx32[N_EDGES + ec1];
    }

    u64 o[2][OUT_CH / 2];
    {
        const ulonglong2* bp = reinterpret_cast<const ulonglong2*>(sb2);
#pragma unroll
        for (int j = 0; j < OUT_CH / 4; j++) {
            ulonglong2 v = bp[j];
            o[0][2 * j] = v.x; o[0][2 * j + 1] = v.y;
            o[1][2 * j] = v.x; o[1][2 * j + 1] = v.y;
        }
    }

#pragma unroll
    for (int q = 0; q < 14; q++) {
        float4 h0 = g_H[(size_t)q * N_EDGES + ec0];
        float4 h1 = g_H[(size_t)q * N_EDGES + ec1];
        float s0[4] = {h0.x, h0.y, h0.z, h0.w};
        float s1[4] = {h1.x, h1.y, h1.z, h1.w};
#pragma unroll
        for (int u = 0; u < 4; u++) {
            int k = 4 * q + u;
            u64 aa0 = pk2(s0[u], s0[u]);
            u64 aa1 = pk2(s1[u], s1[u]);
            const ulonglong2* w = reinterpret_cast<const ulonglong2*>(&sW2[k * OUT_CH]);
#pragma unroll
            for (int j = 0; j < OUT_CH / 4; j++) {
                ulonglong2 ww = w[j];                // shared across both edges
                FMA2(o[0][2 * j],     aa0, ww.x, o[0][2 * j]);
                FMA2(o[0][2 * j + 1], aa0, ww.y, o[0][2 * j + 1]);
                FMA2(o[1][2 * j],     aa1, ww.x, o[1][2 * j]);
                FMA2(o[1][2 * j + 1], aa1, ww.y, o[1][2 * j + 1]);
            }
        }
    }

    // LeakyReLU + filtered scatter-max (round-6 epilogue), per edge
#pragma unroll
    for (int i = 0; i < 2; i++) {
        if (i == 0 ? !v0 : !v1) continue;
        int col = (i == 0) ? col0 : col1;
        float* orow = out + (size_t)col * OUT_CH;
        const float4* oro = reinterpret_cast<const float4*>(orow);
#pragma unroll
        for (int q = 0; q < OUT_CH / 4; q++) {
            float w0, w1, w2, w3;
            upk2(w0, w1, o[i][2 * q]);
            upk2(w2, w3, o[i][2 * q + 1]);
            w0 = fmaxf(w0, 0.01f * w0);
            w1 = fmaxf(w1, 0.01f * w1);
            w2 = fmaxf(w2, 0.01f * w2);
            w3 = fmaxf(w3, 0.01f * w3);
            float4 cur = oro[q];                 // monotone max: stale read is safe
            if (w0 > cur.x) atomicMaxF(orow + 4 * q + 0, w0);
            if (w1 > cur.y) atomicMaxF(orow + 4 * q + 1, w1);
            if (w2 > cur.z) atomicMaxF(orow + 4 * q + 2, w2);
            if (w3 > cur.w) atomicMaxF(orow + 4 * q + 3, w3);
        }
    }
}

// ---------------------------------------------------------------------------
// K3: finalize — -inf -> 0, elementwise max with x (float4)
// ---------------------------------------------------------------------------
__global__ void k_final(const float4* __restrict__ x, float4* __restrict__ out) {
    int i = blockIdx.x * blockDim.x + threadIdx.x;
    if (i >= N_NODES * OUT_CH / 4) return;
    float4 a = out[i];
    float4 b = x[i];
    if (__float_as_uint(a.x) == 0xFF800000u) a.x = 0.0f;
    if (__float_as_uint(a.y) == 0xFF800000u) a.y = 0.0f;
    if (__float_as_uint(a.z) == 0xFF800000u) a.z = 0.0f;
    if (__float_as_uint(a.w) == 0xFF800000u) a.w = 0.0f;
    a.x = fmaxf(a.x, b.x); a.y = fmaxf(a.y, b.y);
    a.z = fmaxf(a.z, b.z); a.w = fmaxf(a.w, b.w);
    out[i] = a;
}

// ---------------------------------------------------------------------------
extern "C" void kernel_launch(void* const* d_in, const int* in_sizes, int n_in,
                              void* d_out, int out_size) {
    const float* x         = (const float*)d_in[0];
    const int*   idx32     = (const int*)d_in[1];
    const float* edge_attr = (const float*)d_in[2];
    const float* W1        = (const float*)d_in[3];
    const float* b1        = (const float*)d_in[4];
    const float* W2        = (const float*)d_in[5];
    const float* b2        = (const float*)d_in[6];
    float* out = (float*)d_out;

    const int eg2 = (N_EDGES + 255) / 256;
    k_pre<<<592, 256>>>((const unsigned int*)d_in[1], (unsigned int*)d_out);
    k_node<<<(N_NODES + 127) / 128, 128>>>(x, W1, b1);
    k_e1<<<eg2, 128>>>(idx32, edge_attr, W1);
    k_e2<<<eg2, 128>>>(idx32, W2, b2, out);
    k_final<<<(N_NODES * OUT_CH / 4 + 255) / 256, 256>>>((const float4*)x, (float4*)out);
}